// round 13
// baseline (speedup 1.0000x reference)
#include <cuda_runtime.h>
#include <cuda_bf16.h>
#include <math.h>

#define N_NODES 50000
#define N_EDGES 1600000
#define IN_C 512
#define HID_C 256
#define OUT_C 50
#define HSTRIDE 64
#define NUM_LAYERS 10
#define ALPHA 0.1f

// ---------------- scratch (static device globals only) ----------------
// NOTE: these symbols are ONLY referenced inside device code. Passing them
// as kernel arguments from host code yields the host shadow address (which
// ATS silently accepts on GB300) — that was the R2-R10 bug.
__device__ float      g_h1[(size_t)N_NODES * HID_C];
__device__ float      g_x0[(size_t)N_NODES * HSTRIDE];
__device__ float      g_hA[(size_t)N_NODES * HSTRIDE];
__device__ float      g_hB[(size_t)N_NODES * HSTRIDE];
__device__ int        g_deg[N_NODES];
__device__ int        g_rowptr[N_NODES + 1];
__device__ int        g_cursor[N_NODES];
__device__ long long  g_csr[N_EDGES];     // packed (w_bits<<32)|col

// ---------------------------- CSR build -----------------------------------
__global__ void zero_deg_kernel() {
    int i = blockIdx.x * blockDim.x + threadIdx.x;
    if (i < N_NODES) g_deg[i] = 0;
}

__global__ void hist_kernel(const int* __restrict__ erow) {
    int e = blockIdx.x * blockDim.x + threadIdx.x;
    if (e < N_EDGES) {
        unsigned r = (unsigned)erow[e];
        if (r < N_NODES) atomicAdd(&g_deg[r], 1);
    }
}

__global__ void scan_kernel() {
    __shared__ int sh[1024];
    const int PER = (N_NODES + 1023) / 1024;   // 49
    int t = threadIdx.x;
    int base = t * PER;
    int sum = 0;
    for (int i = 0; i < PER; i++) {
        int idx = base + i;
        if (idx < N_NODES) sum += g_deg[idx];
    }
    sh[t] = sum;
    __syncthreads();
    for (int off = 1; off < 1024; off <<= 1) {
        int add = (t >= off) ? sh[t - off] : 0;
        __syncthreads();
        sh[t] += add;
        __syncthreads();
    }
    int excl = sh[t] - sum;
    int run = excl;
    for (int i = 0; i < PER; i++) {
        int idx = base + i;
        if (idx < N_NODES) {
            g_rowptr[idx] = run;
            g_cursor[idx] = run;
            run += g_deg[idx];
        }
    }
    if (t == 1023) g_rowptr[N_NODES] = excl + sum;
}

__global__ void scatter_kernel(const int* __restrict__ erow,
                               const int* __restrict__ ecol,
                               const float* __restrict__ ew) {
    int e = blockIdx.x * blockDim.x + threadIdx.x;
    if (e >= N_EDGES) return;
    unsigned r = (unsigned)erow[e];
    if (r >= N_NODES) return;
    int pos = atomicAdd(&g_cursor[r], 1);
    long long packed = ((long long)__float_as_int(ew[e]) << 32) | (unsigned int)ecol[e];
    g_csr[pos] = packed;
}

// ------------------------------ GEMM1 --------------------------------------
// g_h1 = relu(X @ W1 + b1)   [50000,512] x [512,256]
#define G1_BM 128
#define G1_BN 64
#define G1_BK 16
#define G1_PAD (G1_BM + 2)

__global__ void __launch_bounds__(256) gemm1_kernel(const float* __restrict__ X,
                                                    const float* __restrict__ W1,
                                                    const float* __restrict__ b1) {
    __shared__ float As[G1_BK][G1_PAD];
    __shared__ float Bs[G1_BK][G1_BN];

    int bm = blockIdx.y * G1_BM;
    int bn = blockIdx.x * G1_BN;
    int tid = threadIdx.x;
    int ty = tid >> 4;
    int tx = tid & 15;

    float acc[8][4];
    #pragma unroll
    for (int i = 0; i < 8; i++)
        #pragma unroll
        for (int j = 0; j < 4; j++) acc[i][j] = 0.f;

    for (int k0 = 0; k0 < IN_C; k0 += G1_BK) {
        #pragma unroll
        for (int i = 0; i < 2; i++) {
            int idx = tid + i * 256;
            int r = idx >> 2;
            int c = idx & 3;
            int grow = bm + r;
            float4 v = make_float4(0.f, 0.f, 0.f, 0.f);
            if (grow < N_NODES)
                v = *(const float4*)&X[(size_t)grow * IN_C + k0 + c * 4];
            As[c * 4 + 0][r] = v.x;
            As[c * 4 + 1][r] = v.y;
            As[c * 4 + 2][r] = v.z;
            As[c * 4 + 3][r] = v.w;
        }
        {
            int r = tid >> 4;
            int c = tid & 15;
            float4 v = *(const float4*)&W1[(size_t)(k0 + r) * HID_C + bn + c * 4];
            *(float4*)&Bs[r][c * 4] = v;
        }
        __syncthreads();

        #pragma unroll
        for (int k = 0; k < G1_BK; k++) {
            float a[8];
            #pragma unroll
            for (int i = 0; i < 8; i++) a[i] = As[k][ty * 8 + i];
            float4 bv = *(const float4*)&Bs[k][tx * 4];
            float b[4] = {bv.x, bv.y, bv.z, bv.w};
            #pragma unroll
            for (int i = 0; i < 8; i++)
                #pragma unroll
                for (int j = 0; j < 4; j++)
                    acc[i][j] = fmaf(a[i], b[j], acc[i][j]);
        }
        __syncthreads();
    }

    float4 bb = *(const float4*)&b1[bn + tx * 4];
    float bias[4] = {bb.x, bb.y, bb.z, bb.w};
    #pragma unroll
    for (int i = 0; i < 8; i++) {
        int grow = bm + ty * 8 + i;
        if (grow < N_NODES) {
            float4 o;
            o.x = fmaxf(acc[i][0] + bias[0], 0.f);
            o.y = fmaxf(acc[i][1] + bias[1], 0.f);
            o.z = fmaxf(acc[i][2] + bias[2], 0.f);
            o.w = fmaxf(acc[i][3] + bias[3], 0.f);
            *(float4*)&g_h1[(size_t)grow * HID_C + bn + tx * 4] = o;
        }
    }
}

// ------------------------------ GEMM2 --------------------------------------
// x0 = g_h1 @ W2 + b2 ; hA = x0.   [50000,256] x [256,50], stride-64 out
__global__ void __launch_bounds__(256) gemm2_kernel(const float* __restrict__ W2,
                                                    const float* __restrict__ b2) {
    int gwarp = (blockIdx.x * blockDim.x + threadIdx.x) >> 5;
    int lane = threadIdx.x & 31;
    const int R = 4;
    int row0 = gwarp * R;
    if (row0 >= N_NODES) return;

    float2 acc[R];
    #pragma unroll
    for (int r = 0; r < R; r++) acc[r] = make_float2(0.f, 0.f);

    for (int kk = 0; kk < HID_C; kk += 32) {
        float hbuf[R];
        #pragma unroll
        for (int r = 0; r < R; r++) {
            int row = row0 + r;
            hbuf[r] = (row < N_NODES) ? g_h1[(size_t)row * HID_C + kk + lane] : 0.f;
        }
        #pragma unroll
        for (int j = 0; j < 32; j++) {
            float2 wv = make_float2(0.f, 0.f);
            if (lane < 25)
                wv = *(const float2*)&W2[(size_t)(kk + j) * OUT_C + 2 * lane];
            #pragma unroll
            for (int r = 0; r < R; r++) {
                float hv = __shfl_sync(0xffffffffu, hbuf[r], j);
                acc[r].x = fmaf(hv, wv.x, acc[r].x);
                acc[r].y = fmaf(hv, wv.y, acc[r].y);
            }
        }
    }

    float2 bb = make_float2(0.f, 0.f);
    if (lane < 25) bb = *(const float2*)&b2[2 * lane];
    #pragma unroll
    for (int r = 0; r < R; r++) {
        int row = row0 + r;
        if (row < N_NODES && lane < 25) {
            float2 o = make_float2(acc[r].x + bb.x, acc[r].y + bb.y);
            *(float2*)&g_x0[((size_t)row << 6) + 2 * lane] = o;
            *(float2*)&g_hA[((size_t)row << 6) + 2 * lane] = o;
        }
    }
}

// ------------------------------ SpMM ---------------------------------------
// flip=0: hB <- 0.9 * A hA + 0.1 x0 ;  flip=1: hA <- 0.9 * A hB + 0.1 x0
// Ping-pong buffers resolved INSIDE device code (never via host symbols).
__global__ void __launch_bounds__(256) spmm_kernel(int flip) {
    const float* __restrict__ hsrc = flip ? g_hB : g_hA;
    float* __restrict__       hdst = flip ? g_hA : g_hB;

    int row = (blockIdx.x * blockDim.x + threadIdx.x) >> 5;
    int lane = threadIdx.x & 31;
    if (row >= N_NODES) return;
    int start = g_rowptr[row];
    int end = g_rowptr[row + 1];

    float acc0 = 0.f, acc1 = 0.f;
    for (int e0 = start; e0 < end; e0 += 32) {
        long long p = 0;
        int e = e0 + lane;
        if (e < end) p = g_csr[e];
        int n = min(32, end - e0);
        for (int j = 0; j < n; j++) {
            long long pj = __shfl_sync(0xffffffffu, p, j);
            int col = (int)((unsigned long long)pj & 0xffffffffull);
            float w = __int_as_float((int)((unsigned long long)pj >> 32));
            const float* hr = hsrc + ((size_t)col << 6);
            acc0 = fmaf(w, hr[lane], acc0);
            if (lane < OUT_C - 32) acc1 = fmaf(w, hr[32 + lane], acc1);
        }
    }
    const float* x0r = g_x0 + ((size_t)row << 6);
    float* outp = hdst + ((size_t)row << 6);
    outp[lane] = (1.0f - ALPHA) * acc0 + ALPHA * x0r[lane];
    if (lane < OUT_C - 32)
        outp[32 + lane] = (1.0f - ALPHA) * acc1 + ALPHA * x0r[32 + lane];
}

// ---------------------------- log_softmax ----------------------------------
// Reads g_hA internally (final state after an even number of rounds).
__global__ void __launch_bounds__(256) lsm_kernel(float* __restrict__ out) {
    int row = (blockIdx.x * blockDim.x + threadIdx.x) >> 5;
    int lane = threadIdx.x & 31;
    if (row >= N_NODES) return;
    const float* hr = g_hA + ((size_t)row << 6);
    float v0 = hr[lane];
    float v1 = (lane < OUT_C - 32) ? hr[32 + lane] : -INFINITY;

    float m = fmaxf(v0, v1);
    #pragma unroll
    for (int o = 16; o > 0; o >>= 1)
        m = fmaxf(m, __shfl_xor_sync(0xffffffffu, m, o));

    float s = expf(v0 - m) + ((lane < OUT_C - 32) ? expf(v1 - m) : 0.f);
    #pragma unroll
    for (int o = 16; o > 0; o >>= 1)
        s += __shfl_xor_sync(0xffffffffu, s, o);

    float ls = m + logf(s);
    out[(size_t)row * OUT_C + lane] = v0 - ls;
    if (lane < OUT_C - 32)
        out[(size_t)row * OUT_C + 32 + lane] = v1 - ls;
}

// ------------------------------- launch -------------------------------------
extern "C" void kernel_launch(void* const* d_in, const int* in_sizes, int n_in,
                              void* d_out, int out_size) {
    // Binding verified by R11 evidence: insertion order.
    const float* x    = (const float*)d_in[0];
    const int*   erow = (const int*)d_in[1];
    const int*   ecol = (const int*)d_in[2];
    const float* ew   = (const float*)d_in[3];
    const float* W1   = (const float*)d_in[4];
    const float* b1   = (const float*)d_in[5];
    const float* W2   = (const float*)d_in[6];
    const float* b2   = (const float*)d_in[7];
    float* out = (float*)d_out;

    // CSR build
    zero_deg_kernel<<<(N_NODES + 255) / 256, 256>>>();
    hist_kernel<<<(N_EDGES + 255) / 256, 256>>>(erow);
    scan_kernel<<<1, 1024>>>();
    scatter_kernel<<<(N_EDGES + 255) / 256, 256>>>(erow, ecol, ew);

    // MLP
    dim3 g1grid(HID_C / G1_BN, (N_NODES + G1_BM - 1) / G1_BM);
    gemm1_kernel<<<g1grid, 256>>>(x, W1, b1);
    int g2warps = (N_NODES + 3) / 4;
    gemm2_kernel<<<(g2warps * 32 + 255) / 256, 256>>>(W2, b2);

    // 10 propagation rounds; flip selects buffers inside device code.
    const int spmm_blocks = (N_NODES * 32 + 255) / 256;
    for (int it = 0; it < NUM_LAYERS; it++)
        spmm_kernel<<<spmm_blocks, 256>>>(it & 1);

    lsm_kernel<<<spmm_blocks, 256>>>(out);
}

// round 15
// speedup vs baseline: 1.1225x; 1.1225x over previous
#include <cuda_runtime.h>
#include <cuda_bf16.h>
#include <math.h>
#include <cstdint>

#define N_NODES 50000
#define N_EDGES 1600000
#define IN_C 512
#define HID_C 256
#define OUT_C 50
#define HSTRIDE 64
#define NUM_LAYERS 10
#define ALPHA 0.1f

// ---------------- scratch (device-code-only symbols) ----------------
__device__ float      g_h1[(size_t)N_NODES * HID_C];
__device__ float      g_x0[(size_t)N_NODES * HSTRIDE];
__device__ float      g_hA[(size_t)N_NODES * HSTRIDE];
__device__ float      g_hB[(size_t)N_NODES * HSTRIDE];
__device__ int        g_deg[N_NODES];
__device__ int        g_rowptr[N_NODES + 1];
__device__ int        g_cursor[N_NODES];
__device__ long long  g_csr[N_EDGES];

// ---------------------------- CSR build -----------------------------------
__global__ void zero_deg_kernel() {
    int i = blockIdx.x * blockDim.x + threadIdx.x;
    if (i < N_NODES) g_deg[i] = 0;
}
__global__ void hist_kernel(const int* __restrict__ erow) {
    int e = blockIdx.x * blockDim.x + threadIdx.x;
    if (e < N_EDGES) {
        unsigned r = (unsigned)erow[e];
        if (r < N_NODES) atomicAdd(&g_deg[r], 1);
    }
}
__global__ void scan_kernel() {
    __shared__ int sh[1024];
    const int PER = (N_NODES + 1023) / 1024;
    int t = threadIdx.x;
    int base = t * PER;
    int sum = 0;
    for (int i = 0; i < PER; i++) {
        int idx = base + i;
        if (idx < N_NODES) sum += g_deg[idx];
    }
    sh[t] = sum;
    __syncthreads();
    for (int off = 1; off < 1024; off <<= 1) {
        int add = (t >= off) ? sh[t - off] : 0;
        __syncthreads();
        sh[t] += add;
        __syncthreads();
    }
    int excl = sh[t] - sum;
    int run = excl;
    for (int i = 0; i < PER; i++) {
        int idx = base + i;
        if (idx < N_NODES) {
            g_rowptr[idx] = run;
            g_cursor[idx] = run;
            run += g_deg[idx];
        }
    }
    if (t == 1023) g_rowptr[N_NODES] = excl + sum;
}
__global__ void scatter_kernel(const int* __restrict__ erow,
                               const int* __restrict__ ecol,
                               const float* __restrict__ ew) {
    int e = blockIdx.x * blockDim.x + threadIdx.x;
    if (e >= N_EDGES) return;
    unsigned r = (unsigned)erow[e];
    if (r >= N_NODES) return;
    int pos = atomicAdd(&g_cursor[r], 1);
    long long packed = ((long long)__float_as_int(ew[e]) << 32) | (unsigned int)ecol[e];
    g_csr[pos] = packed;
}

// ---------------- GEMM1 via mma.sync bf16 hi/lo split -----------------------
// g_h1 = relu(X @ W1 + b1). BM=128, BN=128, BK=32.
// 8 warps, each 64x32 output = 4x4 tiles of m16n8k16.
#define ASTRW 20     // A smem row stride in words (40 bf16, pad 8)
#define BSTRW 68     // B smem row stride in words (136 bf16, pad 8)

__device__ __forceinline__ uint32_t smem_addr_u32(const void* p) {
    uint32_t a;
    asm("{ .reg .u64 t; cvta.to.shared.u64 t, %1; cvt.u32.u64 %0, t; }"
        : "=r"(a) : "l"(p));
    return a;
}
__device__ __forceinline__ void ldsm_x4(uint32_t* r, uint32_t addr) {
    asm volatile("ldmatrix.sync.aligned.m8n8.x4.shared.b16 {%0,%1,%2,%3}, [%4];"
                 : "=r"(r[0]), "=r"(r[1]), "=r"(r[2]), "=r"(r[3]) : "r"(addr));
}
__device__ __forceinline__ void ldsm_x2t(uint32_t* r, uint32_t addr) {
    asm volatile("ldmatrix.sync.aligned.m8n8.x2.trans.shared.b16 {%0,%1}, [%2];"
                 : "=r"(r[0]), "=r"(r[1]) : "r"(addr));
}
__device__ __forceinline__ void mma_bf16(float* d, const uint32_t* a, const uint32_t* b) {
    asm volatile("mma.sync.aligned.m16n8k16.row.col.f32.bf16.bf16.f32 "
                 "{%0,%1,%2,%3}, {%4,%5,%6,%7}, {%8,%9}, {%0,%1,%2,%3};"
                 : "+f"(d[0]), "+f"(d[1]), "+f"(d[2]), "+f"(d[3])
                 : "r"(a[0]), "r"(a[1]), "r"(a[2]), "r"(a[3]), "r"(b[0]), "r"(b[1]));
}
__device__ __forceinline__ uint32_t pack_bf16_hi(float x, float y) {
    __nv_bfloat16 hx = __float2bfloat16(x);
    __nv_bfloat16 hy = __float2bfloat16(y);
    return ((uint32_t)__bfloat16_as_ushort(hy) << 16) | __bfloat16_as_ushort(hx);
}
__device__ __forceinline__ uint32_t pack_bf16_lo(float x, float y) {
    __nv_bfloat16 hx = __float2bfloat16(x);
    __nv_bfloat16 hy = __float2bfloat16(y);
    __nv_bfloat16 lx = __float2bfloat16(x - __bfloat162float(hx));
    __nv_bfloat16 ly = __float2bfloat16(y - __bfloat162float(hy));
    return ((uint32_t)__bfloat16_as_ushort(ly) << 16) | __bfloat16_as_ushort(lx);
}

__global__ void __launch_bounds__(256) gemm1_mma_kernel(
        const float* __restrict__ X, const float* __restrict__ W1,
        const float* __restrict__ b1) {
    __shared__ uint32_t Ah[128 * ASTRW], Al[128 * ASTRW];
    __shared__ uint32_t Bh[32 * BSTRW],  Bl[32 * BSTRW];

    int tid = threadIdx.x;
    int wid = tid >> 5;
    int lane = tid & 31;
    int wm = wid >> 2;          // 0..1 (64 rows each)
    int wn = wid & 3;           // 0..3 (32 cols each)
    int bm = blockIdx.x * 128;
    int bn = blockIdx.y * 128;

    float d[4][4][4];           // [mtile][ntile][frag]
    #pragma unroll
    for (int i = 0; i < 4; i++)
        #pragma unroll
        for (int j = 0; j < 4; j++)
            #pragma unroll
            for (int q = 0; q < 4; q++) d[i][j][q] = 0.f;

    const uint32_t AhB = smem_addr_u32(Ah);
    const uint32_t AlB = smem_addr_u32(Al);
    const uint32_t BhB = smem_addr_u32(Bh);
    const uint32_t BlB = smem_addr_u32(Bl);

    // staging indices
    int s_arow = tid >> 1;             // 0..127
    int s_ak = (tid & 1) * 16;         // 0 or 16
    int s_grow = bm + s_arow;
    int s_bk = tid >> 3;               // 0..31
    int s_bn = (tid & 7) * 16;         // 0..112

    // ldmatrix lane addressing
    int lm_row = ((lane >> 3) & 1) * 8 + (lane & 7);   // within 16-row tile
    int lm_kofs = (lane >> 4) * 8;                     // 0 or 8 (x4 col half)
    int lb_row = (((lane & 15) >> 3)) * 8 + (lane & 7);

    for (int c = 0; c < IN_C / 32; c++) {
        int k0 = c * 32;
        // ---- stage A: X[bm..bm+127][k0..k0+31] -> hi/lo bf16 ----
        {
            const float* src = X + (size_t)s_grow * IN_C + k0 + s_ak;
            #pragma unroll
            for (int f = 0; f < 4; f++) {
                float4 v = make_float4(0.f, 0.f, 0.f, 0.f);
                if (s_grow < N_NODES) v = *(const float4*)(src + f * 4);
                int w = s_arow * ASTRW + ((s_ak + f * 4) >> 1);
                Ah[w]     = pack_bf16_hi(v.x, v.y);
                Ah[w + 1] = pack_bf16_hi(v.z, v.w);
                Al[w]     = pack_bf16_lo(v.x, v.y);
                Al[w + 1] = pack_bf16_lo(v.z, v.w);
            }
        }
        // ---- stage B: W1[k0+k][bn..bn+127] -> [k][n] hi/lo ----
        {
            const float* src = W1 + (size_t)(k0 + s_bk) * HID_C + bn + s_bn;
            #pragma unroll
            for (int f = 0; f < 4; f++) {
                float4 v = *(const float4*)(src + f * 4);
                int w = s_bk * BSTRW + ((s_bn + f * 4) >> 1);
                Bh[w]     = pack_bf16_hi(v.x, v.y);
                Bh[w + 1] = pack_bf16_hi(v.z, v.w);
                Bl[w]     = pack_bf16_lo(v.x, v.y);
                Bl[w + 1] = pack_bf16_lo(v.z, v.w);
            }
        }
        __syncthreads();

        #pragma unroll
        for (int ks = 0; ks < 2; ks++) {
            uint32_t ah[4][4], al[4][4], bh[4][2], bl[4][2];
            #pragma unroll
            for (int mt = 0; mt < 4; mt++) {
                int row = wm * 64 + mt * 16 + lm_row;
                uint32_t off = (uint32_t)(row * ASTRW + ((ks * 16 + lm_kofs) >> 1)) * 4u;
                ldsm_x4(ah[mt], AhB + off);
                ldsm_x4(al[mt], AlB + off);
            }
            #pragma unroll
            for (int nt = 0; nt < 4; nt++) {
                int krow = ks * 16 + lb_row;
                int ncol = wn * 32 + nt * 8;
                uint32_t off = (uint32_t)(krow * BSTRW + (ncol >> 1)) * 4u;
                ldsm_x2t(bh[nt], BhB + off);
                ldsm_x2t(bl[nt], BlB + off);
            }
            #pragma unroll
            for (int mt = 0; mt < 4; mt++)
                #pragma unroll
                for (int nt = 0; nt < 4; nt++) {
                    mma_bf16(d[mt][nt], ah[mt], bh[nt]);
                    mma_bf16(d[mt][nt], ah[mt], bl[nt]);
                    mma_bf16(d[mt][nt], al[mt], bh[nt]);
                }
        }
        __syncthreads();
    }

    // ---- epilogue: bias + relu -> g_h1 ----
    int g = lane >> 2;          // 0..7
    int tg = lane & 3;          // 0..3
    #pragma unroll
    for (int mt = 0; mt < 4; mt++) {
        int r0 = bm + wm * 64 + mt * 16 + g;
        int r1 = r0 + 8;
        #pragma unroll
        for (int nt = 0; nt < 4; nt++) {
            int n = bn + wn * 32 + nt * 8 + tg * 2;
            float2 bb = *(const float2*)&b1[n];
            if (r0 < N_NODES) {
                float2 o;
                o.x = fmaxf(d[mt][nt][0] + bb.x, 0.f);
                o.y = fmaxf(d[mt][nt][1] + bb.y, 0.f);
                *(float2*)&g_h1[(size_t)r0 * HID_C + n] = o;
            }
            if (r1 < N_NODES) {
                float2 o;
                o.x = fmaxf(d[mt][nt][2] + bb.x, 0.f);
                o.y = fmaxf(d[mt][nt][3] + bb.y, 0.f);
                *(float2*)&g_h1[(size_t)r1 * HID_C + n] = o;
            }
        }
    }
}

// ------------------------------ GEMM2 --------------------------------------
__global__ void __launch_bounds__(256) gemm2_kernel(const float* __restrict__ W2,
                                                    const float* __restrict__ b2) {
    int gwarp = (blockIdx.x * blockDim.x + threadIdx.x) >> 5;
    int lane = threadIdx.x & 31;
    const int R = 4;
    int row0 = gwarp * R;
    if (row0 >= N_NODES) return;

    float2 acc[R];
    #pragma unroll
    for (int r = 0; r < R; r++) acc[r] = make_float2(0.f, 0.f);

    for (int kk = 0; kk < HID_C; kk += 32) {
        float hbuf[R];
        #pragma unroll
        for (int r = 0; r < R; r++) {
            int row = row0 + r;
            hbuf[r] = (row < N_NODES) ? g_h1[(size_t)row * HID_C + kk + lane] : 0.f;
        }
        #pragma unroll
        for (int j = 0; j < 32; j++) {
            float2 wv = make_float2(0.f, 0.f);
            if (lane < 25)
                wv = *(const float2*)&W2[(size_t)(kk + j) * OUT_C + 2 * lane];
            #pragma unroll
            for (int r = 0; r < R; r++) {
                float hv = __shfl_sync(0xffffffffu, hbuf[r], j);
                acc[r].x = fmaf(hv, wv.x, acc[r].x);
                acc[r].y = fmaf(hv, wv.y, acc[r].y);
            }
        }
    }

    float2 bb = make_float2(0.f, 0.f);
    if (lane < 25) bb = *(const float2*)&b2[2 * lane];
    #pragma unroll
    for (int r = 0; r < R; r++) {
        int row = row0 + r;
        if (row < N_NODES && lane < 25) {
            float2 o = make_float2(acc[r].x + bb.x, acc[r].y + bb.y);
            *(float2*)&g_x0[((size_t)row << 6) + 2 * lane] = o;
            *(float2*)&g_hA[((size_t)row << 6) + 2 * lane] = o;
        }
    }
}

// ------------------------------ SpMM ---------------------------------------
__global__ void __launch_bounds__(256) spmm_kernel(int flip) {
    const float* __restrict__ hsrc = flip ? g_hB : g_hA;
    float* __restrict__       hdst = flip ? g_hA : g_hB;

    int row = (blockIdx.x * blockDim.x + threadIdx.x) >> 5;
    int lane = threadIdx.x & 31;
    if (row >= N_NODES) return;
    int start = g_rowptr[row];
    int end = g_rowptr[row + 1];

    float acc0 = 0.f, acc1 = 0.f;
    for (int e0 = start; e0 < end; e0 += 32) {
        long long p = 0;
        int e = e0 + lane;
        if (e < end) p = g_csr[e];
        int n = min(32, end - e0);
        for (int j = 0; j < n; j++) {
            long long pj = __shfl_sync(0xffffffffu, p, j);
            int col = (int)((unsigned long long)pj & 0xffffffffull);
            float w = __int_as_float((int)((unsigned long long)pj >> 32));
            const float* hr = hsrc + ((size_t)col << 6);
            acc0 = fmaf(w, hr[lane], acc0);
            if (lane < OUT_C - 32) acc1 = fmaf(w, hr[32 + lane], acc1);
        }
    }
    const float* x0r = g_x0 + ((size_t)row << 6);
    float* outp = hdst + ((size_t)row << 6);
    outp[lane] = (1.0f - ALPHA) * acc0 + ALPHA * x0r[lane];
    if (lane < OUT_C - 32)
        outp[32 + lane] = (1.0f - ALPHA) * acc1 + ALPHA * x0r[32 + lane];
}

// ---------------------------- log_softmax ----------------------------------
__global__ void __launch_bounds__(256) lsm_kernel(float* __restrict__ out) {
    int row = (blockIdx.x * blockDim.x + threadIdx.x) >> 5;
    int lane = threadIdx.x & 31;
    if (row >= N_NODES) return;
    const float* hr = g_hA + ((size_t)row << 6);
    float v0 = hr[lane];
    float v1 = (lane < OUT_C - 32) ? hr[32 + lane] : -INFINITY;

    float m = fmaxf(v0, v1);
    #pragma unroll
    for (int o = 16; o > 0; o >>= 1)
        m = fmaxf(m, __shfl_xor_sync(0xffffffffu, m, o));

    float s = expf(v0 - m) + ((lane < OUT_C - 32) ? expf(v1 - m) : 0.f);
    #pragma unroll
    for (int o = 16; o > 0; o >>= 1)
        s += __shfl_xor_sync(0xffffffffu, s, o);

    float ls = m + logf(s);
    out[(size_t)row * OUT_C + lane] = v0 - ls;
    if (lane < OUT_C - 32)
        out[(size_t)row * OUT_C + 32 + lane] = v1 - ls;
}

// ------------------------------- launch -------------------------------------
extern "C" void kernel_launch(void* const* d_in, const int* in_sizes, int n_in,
                              void* d_out, int out_size) {
    const float* x    = (const float*)d_in[0];
    const int*   erow = (const int*)d_in[1];
    const int*   ecol = (const int*)d_in[2];
    const float* ew   = (const float*)d_in[3];
    const float* W1   = (const float*)d_in[4];
    const float* b1   = (const float*)d_in[5];
    const float* W2   = (const float*)d_in[6];
    const float* b2   = (const float*)d_in[7];
    float* out = (float*)d_out;

    // CSR build
    zero_deg_kernel<<<(N_NODES + 255) / 256, 256>>>();
    hist_kernel<<<(N_EDGES + 255) / 256, 256>>>(erow);
    scan_kernel<<<1, 1024>>>();
    scatter_kernel<<<(N_EDGES + 255) / 256, 256>>>(erow, ecol, ew);

    // MLP layer 1 via HMMA bf16 hi/lo (tensor pipe), fused bias+relu
    dim3 g1grid((N_NODES + 127) / 128, HID_C / 128);
    gemm1_mma_kernel<<<g1grid, 256>>>(x, W1, b1);

    // MLP layer 2
    int g2warps = (N_NODES + 3) / 4;
    gemm2_kernel<<<(g2warps * 32 + 255) / 256, 256>>>(W2, b2);

    // 10 propagation rounds (device-side ping-pong)
    const int spmm_blocks = (N_NODES * 32 + 255) / 256;
    for (int it = 0; it < NUM_LAYERS; it++)
        spmm_kernel<<<spmm_blocks, 256>>>(it & 1);

    lsm_kernel<<<spmm_blocks, 256>>>(out);
}